// round 2
// baseline (speedup 1.0000x reference)
#include <cuda_runtime.h>
#include <cstdint>

#define TT 2048   // tokens
#define DD 2048   // model dim
#define NE 16     // experts
#define HH 1024   // expert hidden
#define KK 4      // top-k

#define BM 128
#define BKD 16
#define LDA 132   // padded smem leading dim

// ---- device scratch (static: no allocations allowed) ----
__device__ int   g_cnt[NE];
__device__ int   g_list[NE * TT];            // encoded t*4+slot, gathered per expert
__device__ float g_wt[TT * KK];              // routing weight per (token, slot)
__device__ float g_act[(size_t)TT * KK * HH];   // gated activations, routed (32MB)
__device__ float g_sact[(size_t)TT * HH];       // gated activations, shared (8MB)

__global__ void zero_cnt_kernel() {
    if (threadIdx.x < NE) g_cnt[threadIdx.x] = 0;
}

// ---- gate: logits -> softmax -> top4 -> scatter to per-expert lists ----
__global__ void gate_kernel(const float* __restrict__ x, const float* __restrict__ gw) {
    int gwarp = (blockIdx.x * blockDim.x + threadIdx.x) >> 5;
    int lane  = threadIdx.x & 31;
    if (gwarp >= TT) return;
    const float* xr = x + (size_t)gwarp * DD;
    float acc[NE];
#pragma unroll
    for (int e = 0; e < NE; e++) acc[e] = 0.f;
    for (int d = lane; d < DD; d += 32) {
        float xv = xr[d];
#pragma unroll
        for (int e = 0; e < NE; e++) acc[e] += xv * gw[e * DD + d];
    }
#pragma unroll
    for (int e = 0; e < NE; e++) {
#pragma unroll
        for (int off = 16; off > 0; off >>= 1)
            acc[e] += __shfl_xor_sync(0xffffffffu, acc[e], off);
    }
    if (lane == 0) {
        float m = acc[0];
#pragma unroll
        for (int e = 1; e < NE; e++) m = fmaxf(m, acc[e]);
        float p[NE];
        float s = 0.f;
#pragma unroll
        for (int e = 0; e < NE; e++) { p[e] = __expf(acc[e] - m); s += p[e]; }
        float inv = 1.f / s;
#pragma unroll
        for (int e = 0; e < NE; e++) p[e] *= inv;
#pragma unroll
        for (int k = 0; k < KK; k++) {
            int best = 0; float bv = -1.f;
#pragma unroll
            for (int e = 0; e < NE; e++) {
                if (p[e] > bv) { bv = p[e]; best = e; }
            }
            p[best] = -2.f;
            int pos = atomicAdd(&g_cnt[best], 1);
            g_list[best * TT + pos] = gwarp * KK + k;
            g_wt[gwarp * KK + k]    = bv;
        }
    }
}

// ---- fc1 + fused SiLU gating ----
// Block computes 128 gathered rows x 64 gated output cols.
// B tile packs w1 rows [n0, n0+64) (value) and [H+n0, H+n0+64) (gate) so the
// epilogue can form act = v * silu(g) with no intermediate buffer.
__global__ __launch_bounds__(256, 2) void fc1_kernel(
    const float* __restrict__ x, const float* __restrict__ w1, int shared_mode) {
    int e  = blockIdx.z;
    int n0 = blockIdx.x * 64;
    int r0 = blockIdx.y * BM;
    int cnt;
    const float* wbase;
    float* actout;
    if (shared_mode) { cnt = TT; wbase = w1; actout = g_sact; }
    else {
        cnt = g_cnt[e];
        if (r0 >= cnt) return;
        wbase = w1 + (size_t)e * 2 * HH * DD;
        actout = g_act;
    }

    __shared__ float As[BKD][LDA];
    __shared__ float Bs[BKD][LDA];
    int tid = threadIdx.x;
    int kslot = tid & 3;
    int ra0 = tid >> 2;       // 0..63
    int ra1 = ra0 + 64;

    const float* pa0;
    const float* pa1;
    {
        int rr = r0 + ra0;
        if (shared_mode)      pa0 = x + (size_t)rr * DD;
        else if (rr < cnt)    pa0 = x + (size_t)(g_list[e * TT + rr] >> 2) * DD;
        else                  pa0 = x;
        rr = r0 + ra1;
        if (shared_mode)      pa1 = x + (size_t)rr * DD;
        else if (rr < cnt)    pa1 = x + (size_t)(g_list[e * TT + rr] >> 2) * DD;
        else                  pa1 = x;
    }
    pa0 += kslot * 4; pa1 += kslot * 4;
    int rb = tid >> 2;        // 0..63
    const float* pbv = wbase + (size_t)(n0 + rb) * DD + kslot * 4;        // value rows
    const float* pbg = wbase + (size_t)(HH + n0 + rb) * DD + kslot * 4;   // gate rows

    int ty = tid >> 4, tx = tid & 15;
    float accv[8][8];
#pragma unroll
    for (int i = 0; i < 8; i++)
#pragma unroll
        for (int j = 0; j < 8; j++) accv[i][j] = 0.f;

    for (int k0 = 0; k0 < DD; k0 += BKD) {
        float4 a0 = *(const float4*)(pa0 + k0);
        float4 a1 = *(const float4*)(pa1 + k0);
        float4 b0 = *(const float4*)(pbv + k0);
        float4 b1 = *(const float4*)(pbg + k0);
        int kb = kslot * 4;
        As[kb + 0][ra0] = a0.x; As[kb + 1][ra0] = a0.y; As[kb + 2][ra0] = a0.z; As[kb + 3][ra0] = a0.w;
        As[kb + 0][ra1] = a1.x; As[kb + 1][ra1] = a1.y; As[kb + 2][ra1] = a1.z; As[kb + 3][ra1] = a1.w;
        Bs[kb + 0][rb] = b0.x; Bs[kb + 1][rb] = b0.y; Bs[kb + 2][rb] = b0.z; Bs[kb + 3][rb] = b0.w;
        Bs[kb + 0][64 + rb] = b1.x; Bs[kb + 1][64 + rb] = b1.y; Bs[kb + 2][64 + rb] = b1.z; Bs[kb + 3][64 + rb] = b1.w;
        __syncthreads();
#pragma unroll
        for (int kk = 0; kk < BKD; kk++) {
            float4 av0 = *(const float4*)&As[kk][ty * 8];
            float4 av1 = *(const float4*)&As[kk][ty * 8 + 4];
            float4 bv0 = *(const float4*)&Bs[kk][tx * 4];
            float4 bv1 = *(const float4*)&Bs[kk][64 + tx * 4];
            float a[8] = {av0.x, av0.y, av0.z, av0.w, av1.x, av1.y, av1.z, av1.w};
            float b[8] = {bv0.x, bv0.y, bv0.z, bv0.w, bv1.x, bv1.y, bv1.z, bv1.w};
#pragma unroll
            for (int i = 0; i < 8; i++)
#pragma unroll
                for (int j = 0; j < 8; j++) accv[i][j] += a[i] * b[j];
        }
        __syncthreads();
    }

#pragma unroll
    for (int i = 0; i < 8; i++) {
        int rgl = r0 + ty * 8 + i;
        if (rgl >= cnt) continue;
        int outrow = shared_mode ? rgl : g_list[e * TT + rgl];
        float4 o;
        {
            float g0 = accv[i][4], g1 = accv[i][5], g2 = accv[i][6], g3 = accv[i][7];
            o.x = accv[i][0] * (g0 / (1.f + __expf(-g0)));
            o.y = accv[i][1] * (g1 / (1.f + __expf(-g1)));
            o.z = accv[i][2] * (g2 / (1.f + __expf(-g2)));
            o.w = accv[i][3] * (g3 / (1.f + __expf(-g3)));
        }
        *(float4*)&actout[(size_t)outrow * HH + n0 + tx * 4] = o;
    }
}

// ---- fc2: act @ w2^T ; shared writes, routed atomic-accumulates scaled by weight ----
__global__ __launch_bounds__(256, 2) void fc2_kernel(
    const float* __restrict__ w2, float* __restrict__ z, int shared_mode) {
    int e  = blockIdx.z;
    int n0 = blockIdx.x * BM;   // over D
    int r0 = blockIdx.y * BM;
    int cnt;
    const float* wbase;
    const float* act;
    if (shared_mode) { cnt = TT; wbase = w2; act = g_sact; }
    else {
        cnt = g_cnt[e];
        if (r0 >= cnt) return;
        wbase = w2 + (size_t)e * DD * HH;
        act = g_act;
    }

    __shared__ float As[BKD][LDA];
    __shared__ float Bs[BKD][LDA];
    int tid = threadIdx.x;
    int kslot = tid & 3;
    int ra0 = tid >> 2;
    int ra1 = ra0 + 64;
    const float* pa0;
    const float* pa1;
    {
        int rr = r0 + ra0;
        if (shared_mode)   pa0 = act + (size_t)rr * HH;
        else if (rr < cnt) pa0 = act + (size_t)g_list[e * TT + rr] * HH;
        else               pa0 = act;
        rr = r0 + ra1;
        if (shared_mode)   pa1 = act + (size_t)rr * HH;
        else if (rr < cnt) pa1 = act + (size_t)g_list[e * TT + rr] * HH;
        else               pa1 = act;
    }
    pa0 += kslot * 4; pa1 += kslot * 4;
    int rb0 = tid >> 2;
    const float* pb0 = wbase + (size_t)(n0 + rb0) * HH + kslot * 4;
    const float* pb1 = wbase + (size_t)(n0 + rb0 + 64) * HH + kslot * 4;

    int ty = tid >> 4, tx = tid & 15;
    float accv[8][8];
#pragma unroll
    for (int i = 0; i < 8; i++)
#pragma unroll
        for (int j = 0; j < 8; j++) accv[i][j] = 0.f;

    for (int k0 = 0; k0 < HH; k0 += BKD) {
        float4 a0 = *(const float4*)(pa0 + k0);
        float4 a1 = *(const float4*)(pa1 + k0);
        float4 b0 = *(const float4*)(pb0 + k0);
        float4 b1 = *(const float4*)(pb1 + k0);
        int kb = kslot * 4;
        As[kb + 0][ra0] = a0.x; As[kb + 1][ra0] = a0.y; As[kb + 2][ra0] = a0.z; As[kb + 3][ra0] = a0.w;
        As[kb + 0][ra1] = a1.x; As[kb + 1][ra1] = a1.y; As[kb + 2][ra1] = a1.z; As[kb + 3][ra1] = a1.w;
        Bs[kb + 0][rb0] = b0.x; Bs[kb + 1][rb0] = b0.y; Bs[kb + 2][rb0] = b0.z; Bs[kb + 3][rb0] = b0.w;
        Bs[kb + 0][64 + rb0] = b1.x; Bs[kb + 1][64 + rb0] = b1.y; Bs[kb + 2][64 + rb0] = b1.z; Bs[kb + 3][64 + rb0] = b1.w;
        __syncthreads();
#pragma unroll
        for (int kk = 0; kk < BKD; kk++) {
            float4 av0 = *(const float4*)&As[kk][ty * 8];
            float4 av1 = *(const float4*)&As[kk][ty * 8 + 4];
            float4 bv0 = *(const float4*)&Bs[kk][tx * 8];
            float4 bv1 = *(const float4*)&Bs[kk][tx * 8 + 4];
            float a[8] = {av0.x, av0.y, av0.z, av0.w, av1.x, av1.y, av1.z, av1.w};
            float b[8] = {bv0.x, bv0.y, bv0.z, bv0.w, bv1.x, bv1.y, bv1.z, bv1.w};
#pragma unroll
            for (int i = 0; i < 8; i++)
#pragma unroll
                for (int j = 0; j < 8; j++) accv[i][j] += a[i] * b[j];
        }
        __syncthreads();
    }

#pragma unroll
    for (int i = 0; i < 8; i++) {
        int rgl = r0 + ty * 8 + i;
        if (rgl >= cnt) continue;
        if (shared_mode) {
            float* zr = z + (size_t)rgl * DD + n0 + tx * 8;
            float4 o0 = {accv[i][0], accv[i][1], accv[i][2], accv[i][3]};
            float4 o1 = {accv[i][4], accv[i][5], accv[i][6], accv[i][7]};
            *(float4*)zr = o0;
            *(float4*)(zr + 4) = o1;
        } else {
            int v = g_list[e * TT + rgl];
            int t = v >> 2;
            float w = g_wt[v];
            float* zr = z + (size_t)t * DD + n0 + tx * 8;
#pragma unroll
            for (int j = 0; j < 8; j++) atomicAdd(zr + j, accv[i][j] * w);
        }
    }
}

extern "C" void kernel_launch(void* const* d_in, const int* in_sizes, int n_in,
                              void* d_out, int out_size) {
    const float* x   = (const float*)d_in[0];
    const float* gw  = (const float*)d_in[1];
    const float* w1  = (const float*)d_in[2];
    const float* w2  = (const float*)d_in[3];
    const float* sw1 = (const float*)d_in[4];
    const float* sw2 = (const float*)d_in[5];
    float* z = (float*)d_out;

    zero_cnt_kernel<<<1, 32>>>();
    gate_kernel<<<TT / 8, 256>>>(x, gw);                 // 8 warps/block, 1 warp/token
    fc1_kernel<<<dim3(16, 16, NE), 256>>>(x, w1, 0);     // routed fc1 + silu gating
    fc1_kernel<<<dim3(16, 16, 1), 256>>>(x, sw1, 1);     // shared fc1 + silu gating
    fc2_kernel<<<dim3(16, 16, 1), 256>>>(sw2, z, 1);     // shared fc2 (plain writes, covers all T*D)
    fc2_kernel<<<dim3(16, 16, NE), 256>>>(w2, z, 0);     // routed fc2 (atomic accumulate)
}

// round 4
// speedup vs baseline: 1.8466x; 1.8466x over previous
#include <cuda_runtime.h>
#include <cuda_bf16.h>
#include <cstdint>

#define TT 2048   // tokens
#define DD 2048   // model dim
#define NE 16     // experts
#define HH 1024   // expert hidden
#define KK 4      // top-k

#define KC 32           // K floats per chunk
#define RS 80           // smem row stride in bytes (32 bf16 = 64B + 16B pad)
#define MATB (128 * RS) // one 128xKC bf16 matrix = 10240 B
#define STAGEB (4 * MATB)
#define SMEM_DYN (2 * STAGEB)   // 81920 B

// ---- device scratch ----
__device__ int   g_cnt[NE];
__device__ int   g_list[NE * TT];            // encoded t*KK+slot per expert
__device__ float g_wt[TT * KK];
__device__ float g_act[(size_t)TT * KK * HH];
__device__ float g_sact[(size_t)TT * HH];

// =================== helpers ===================
__device__ __forceinline__ uint32_t s2u(const void* p) {
    uint32_t a;
    asm("{ .reg .u64 t; cvta.to.shared.u64 t, %1; cvt.u32.u64 %0, t; }" : "=r"(a) : "l"(p));
    return a;
}
__device__ __forceinline__ void ldmx4(uint32_t* r, uint32_t a) {
    asm volatile("ldmatrix.sync.aligned.m8n8.x4.shared.b16 {%0,%1,%2,%3}, [%4];"
                 : "=r"(r[0]), "=r"(r[1]), "=r"(r[2]), "=r"(r[3]) : "r"(a));
}
__device__ __forceinline__ void mma16816(float* d, const uint32_t* a, const uint32_t* b) {
    asm volatile(
        "mma.sync.aligned.m16n8k16.row.col.f32.bf16.bf16.f32 "
        "{%0,%1,%2,%3}, {%4,%5,%6,%7}, {%8,%9}, {%0,%1,%2,%3};"
        : "+f"(d[0]), "+f"(d[1]), "+f"(d[2]), "+f"(d[3])
        : "r"(a[0]), "r"(a[1]), "r"(a[2]), "r"(a[3]), "r"(b[0]), "r"(b[1]));
}
__device__ __forceinline__ uint32_t pk2(__nv_bfloat16 a, __nv_bfloat16 b) {
    return (uint32_t)__bfloat16_as_ushort(a) | ((uint32_t)__bfloat16_as_ushort(b) << 16);
}
__device__ __forceinline__ void cvt_split4(float4 v, uint2& hi, uint2& lo) {
    __nv_bfloat16 h0 = __float2bfloat16(v.x), h1 = __float2bfloat16(v.y);
    __nv_bfloat16 h2 = __float2bfloat16(v.z), h3 = __float2bfloat16(v.w);
    __nv_bfloat16 l0 = __float2bfloat16(v.x - __bfloat162float(h0));
    __nv_bfloat16 l1 = __float2bfloat16(v.y - __bfloat162float(h1));
    __nv_bfloat16 l2 = __float2bfloat16(v.z - __bfloat162float(h2));
    __nv_bfloat16 l3 = __float2bfloat16(v.w - __bfloat162float(h3));
    hi.x = pk2(h0, h1); hi.y = pk2(h2, h3);
    lo.x = pk2(l0, l1); lo.y = pk2(l2, l3);
}

// =================== gate ===================
__global__ void zero_cnt_kernel() {
    if (threadIdx.x < NE) g_cnt[threadIdx.x] = 0;
}

__global__ void gate_kernel(const float* __restrict__ x, const float* __restrict__ gw) {
    int gwarp = (blockIdx.x * blockDim.x + threadIdx.x) >> 5;
    int lane  = threadIdx.x & 31;
    if (gwarp >= TT) return;
    const float* xr = x + (size_t)gwarp * DD;
    float acc[NE];
#pragma unroll
    for (int e = 0; e < NE; e++) acc[e] = 0.f;
    for (int d = lane; d < DD; d += 32) {
        float xv = xr[d];
#pragma unroll
        for (int e = 0; e < NE; e++) acc[e] += xv * gw[e * DD + d];
    }
#pragma unroll
    for (int e = 0; e < NE; e++) {
#pragma unroll
        for (int off = 16; off > 0; off >>= 1)
            acc[e] += __shfl_xor_sync(0xffffffffu, acc[e], off);
    }
    if (lane == 0) {
        float m = acc[0];
#pragma unroll
        for (int e = 1; e < NE; e++) m = fmaxf(m, acc[e]);
        float p[NE]; float s = 0.f;
#pragma unroll
        for (int e = 0; e < NE; e++) { p[e] = __expf(acc[e] - m); s += p[e]; }
        float inv = 1.f / s;
#pragma unroll
        for (int e = 0; e < NE; e++) p[e] *= inv;
#pragma unroll
        for (int k = 0; k < KK; k++) {
            int best = 0; float bv = -1.f;
#pragma unroll
            for (int e = 0; e < NE; e++) if (p[e] > bv) { bv = p[e]; best = e; }
            p[best] = -2.f;
            int pos = atomicAdd(&g_cnt[best], 1);
            g_list[best * TT + pos] = gwarp * KK + k;
            g_wt[gwarp * KK + k]    = bv;
        }
    }
}

// =================== HMMA GEMM (split-bf16, fp32 accum) ===================
// Block tile 128x128, KC=32, 2-stage double buffer.
// FC1: B rows interleaved (even=value, odd=gate) -> (v,g) land in adjacent
//      accumulator registers of the same thread -> fused SiLU epilogue.
// FC2: shared mode plain stores; routed mode weighted atomicAdd into z.
template <bool FC1>
__global__ __launch_bounds__(256, 1) void gemm_kernel(
    const float* __restrict__ Ain, const float* __restrict__ W,
    float* __restrict__ out, int shared_mode)
{
    const int KS  = FC1 ? DD : HH;
    const int NCH = KS / KC;
    int e  = blockIdx.z;
    int nb = blockIdx.x;            // FC1: 64 hidden units; FC2: 128 output dims
    int r0 = blockIdx.y * 128;

    int cnt; const float* wb;
    if (shared_mode) { cnt = TT; wb = W; }
    else {
        cnt = g_cnt[e];
        if (r0 >= cnt) return;
        wb = W + (size_t)e * (FC1 ? (size_t)2 * HH * DD : (size_t)DD * HH);
    }
    const float* Abase = FC1 ? Ain : (shared_mode ? g_sact : g_act);

    extern __shared__ char sm[];
    uint32_t smb = s2u(sm);
    int tid = threadIdx.x, lane = tid & 31, wid = tid >> 5;
    int warpM = wid >> 1, warpN = wid & 1;

    // ---- loader setup: each thread loads 4 float4 per matrix per chunk ----
    const float* arp[4]; const float* brp[4]; uint32_t sof[4];
    int cg = tid & 7;
#pragma unroll
    for (int i = 0; i < 4; i++) {
        int rowt = (tid >> 3) + 32 * i;
        sof[i] = rowt * RS + cg * 8;
        int r = r0 + rowt;
        int ar;
        if (shared_mode) ar = r;
        else ar = (r < cnt) ? (FC1 ? (g_list[e * TT + r] >> 2) : g_list[e * TT + r]) : 0;
        arp[i] = Abase + (size_t)ar * KS + cg * 4;
        int brow;
        if (FC1) brow = (rowt & 1) ? (HH + nb * 64 + (rowt >> 1)) : (nb * 64 + (rowt >> 1));
        else     brow = nb * 128 + rowt;
        brp[i] = wb + (size_t)brow * KS + cg * 4;
    }

    // ---- ldmatrix address bases ----
    uint32_t aoff = (uint32_t)((warpM * 32 + (lane & 15)) * RS + (lane >> 4) * 16);
    uint32_t boff = (uint32_t)((warpN * 64 + (lane & 7) + ((lane >> 4) & 1) * 8) * RS
                               + ((lane >> 3) & 1) * 16);

    float acc[2][8][4];
#pragma unroll
    for (int mf = 0; mf < 2; mf++)
#pragma unroll
        for (int nf = 0; nf < 8; nf++)
#pragma unroll
            for (int j = 0; j < 4; j++) acc[mf][nf][j] = 0.f;

    // ---- preload chunk 0 ----
    float4 pa[4], pb[4];
#pragma unroll
    for (int i = 0; i < 4; i++) { pa[i] = *(const float4*)arp[i]; pb[i] = *(const float4*)brp[i]; }
    {
        char* st = sm;
#pragma unroll
        for (int i = 0; i < 4; i++) {
            uint2 hi, lo;
            cvt_split4(pa[i], hi, lo);
            *(uint2*)(st + sof[i]) = hi;
            *(uint2*)(st + MATB + sof[i]) = lo;
            cvt_split4(pb[i], hi, lo);
            *(uint2*)(st + 2 * MATB + sof[i]) = hi;
            *(uint2*)(st + 3 * MATB + sof[i]) = lo;
        }
    }
    __syncthreads();

    for (int c = 0; c < NCH; c++) {
        int s = c & 1;
        if (c + 1 < NCH) {
            int koff = (c + 1) * KC;
#pragma unroll
            for (int i = 0; i < 4; i++) {
                pa[i] = *(const float4*)(arp[i] + koff);
                pb[i] = *(const float4*)(brp[i] + koff);
            }
        }
        // ---- compute on stage s ----
        uint32_t base = smb + s * STAGEB;
#pragma unroll
        for (int ks = 0; ks < 2; ks++) {
            uint32_t ah[2][4], al[2][4];
            ldmx4(ah[0], base + aoff + ks * 32);
            ldmx4(ah[1], base + aoff + 16 * RS + ks * 32);
            ldmx4(al[0], base + MATB + aoff + ks * 32);
            ldmx4(al[1], base + MATB + aoff + 16 * RS + ks * 32);
            uint32_t bh[8][2], bl[8][2];
#pragma unroll
            for (int g = 0; g < 4; g++) {
                uint32_t t[4];
                ldmx4(t, base + 2 * MATB + boff + g * 16 * RS + ks * 32);
                bh[2 * g][0] = t[0]; bh[2 * g][1] = t[1];
                bh[2 * g + 1][0] = t[2]; bh[2 * g + 1][1] = t[3];
                ldmx4(t, base + 3 * MATB + boff + g * 16 * RS + ks * 32);
                bl[2 * g][0] = t[0]; bl[2 * g][1] = t[1];
                bl[2 * g + 1][0] = t[2]; bl[2 * g + 1][1] = t[3];
            }
#pragma unroll
            for (int mf = 0; mf < 2; mf++)
#pragma unroll
                for (int nf = 0; nf < 8; nf++) {
                    mma16816(acc[mf][nf], ah[mf], bh[nf]);
                    mma16816(acc[mf][nf], ah[mf], bl[nf]);
                    mma16816(acc[mf][nf], al[mf], bh[nf]);
                }
        }
        if (c + 1 < NCH) {
            char* st = sm + ((c + 1) & 1) * STAGEB;
#pragma unroll
            for (int i = 0; i < 4; i++) {
                uint2 hi, lo;
                cvt_split4(pa[i], hi, lo);
                *(uint2*)(st + sof[i]) = hi;
                *(uint2*)(st + MATB + sof[i]) = lo;
                cvt_split4(pb[i], hi, lo);
                *(uint2*)(st + 2 * MATB + sof[i]) = hi;
                *(uint2*)(st + 3 * MATB + sof[i]) = lo;
            }
            __syncthreads();
        }
    }

    // ---- epilogue ----
    if (FC1) {
        float* actout = shared_mode ? g_sact : g_act;
#pragma unroll
        for (int mf = 0; mf < 2; mf++) {
            int rA = r0 + warpM * 32 + mf * 16 + (lane >> 2);
#pragma unroll
            for (int nf = 0; nf < 8; nf++) {
                int h = nb * 64 + warpN * 32 + nf * 4 + (lane & 3);
                if (rA < cnt) {
                    int orow = shared_mode ? rA : g_list[e * TT + rA];
                    float g = acc[mf][nf][1];
                    actout[(size_t)orow * HH + h] = acc[mf][nf][0] * (g / (1.f + __expf(-g)));
                }
                int r2 = rA + 8;
                if (r2 < cnt) {
                    int orow = shared_mode ? r2 : g_list[e * TT + r2];
                    float g = acc[mf][nf][3];
                    actout[(size_t)orow * HH + h] = acc[mf][nf][2] * (g / (1.f + __expf(-g)));
                }
            }
        }
    } else {
#pragma unroll
        for (int mf = 0; mf < 2; mf++) {
            int rA = r0 + warpM * 32 + mf * 16 + (lane >> 2);
#pragma unroll
            for (int nf = 0; nf < 8; nf++) {
                int col = nb * 128 + warpN * 64 + nf * 8 + (lane & 3) * 2;
                if (shared_mode) {
                    float2 o0 = { acc[mf][nf][0], acc[mf][nf][1] };
                    float2 o1 = { acc[mf][nf][2], acc[mf][nf][3] };
                    *(float2*)(out + (size_t)rA * DD + col) = o0;
                    *(float2*)(out + (size_t)(rA + 8) * DD + col) = o1;
                } else {
                    if (rA < cnt) {
                        int v = g_list[e * TT + rA];
                        float w = g_wt[v];
                        float* zr = out + (size_t)(v >> 2) * DD + col;
                        atomicAdd(zr,     acc[mf][nf][0] * w);
                        atomicAdd(zr + 1, acc[mf][nf][1] * w);
                    }
                    int r2 = rA + 8;
                    if (r2 < cnt) {
                        int v = g_list[e * TT + r2];
                        float w = g_wt[v];
                        float* zr = out + (size_t)(v >> 2) * DD + col;
                        atomicAdd(zr,     acc[mf][nf][2] * w);
                        atomicAdd(zr + 1, acc[mf][nf][3] * w);
                    }
                }
            }
        }
    }
}

// =================== host launch ===================
extern "C" void kernel_launch(void* const* d_in, const int* in_sizes, int n_in,
                              void* d_out, int out_size) {
    const float* x   = (const float*)d_in[0];
    const float* gw  = (const float*)d_in[1];
    const float* w1  = (const float*)d_in[2];
    const float* w2  = (const float*)d_in[3];
    const float* sw1 = (const float*)d_in[4];
    const float* sw2 = (const float*)d_in[5];
    float* z = (float*)d_out;

    cudaFuncSetAttribute(gemm_kernel<true>,  cudaFuncAttributeMaxDynamicSharedMemorySize, SMEM_DYN);
    cudaFuncSetAttribute(gemm_kernel<false>, cudaFuncAttributeMaxDynamicSharedMemorySize, SMEM_DYN);

    zero_cnt_kernel<<<1, 32>>>();
    gate_kernel<<<TT / 8, 256>>>(x, gw);
    // routed fc1 + fused silu -> g_act
    gemm_kernel<true><<<dim3(HH / 64, 16, NE), 256, SMEM_DYN>>>(x, w1, nullptr, 0);
    // shared fc1 + fused silu -> g_sact
    gemm_kernel<true><<<dim3(HH / 64, 16, 1), 256, SMEM_DYN>>>(x, sw1, nullptr, 1);
    // shared fc2 -> z (plain stores, initializes every output element)
    gemm_kernel<false><<<dim3(DD / 128, 16, 1), 256, SMEM_DYN>>>(nullptr, sw2, z, 1);
    // routed fc2 -> z (weighted atomic accumulate)
    gemm_kernel<false><<<dim3(DD / 128, 16, NE), 256, SMEM_DYN>>>(nullptr, w2, z, 0);
}